// round 1
// baseline (speedup 1.0000x reference)
#include <cuda_runtime.h>

#define T_STEPS 512
#define HID 16

// ---------- packed f32x2 helpers (Blackwell FFMA2 path) ----------
__device__ __forceinline__ unsigned long long pk2(float a, float b) {
    unsigned long long r;
    asm("mov.b64 %0, {%1,%2};" : "=l"(r) : "f"(a), "f"(b));
    return r;
}
__device__ __forceinline__ void upk2(unsigned long long v, float& a, float& b) {
    asm("mov.b64 {%0,%1}, %2;" : "=f"(a), "=f"(b) : "l"(v));
}
__device__ __forceinline__ unsigned long long fma2(unsigned long long a,
                                                   unsigned long long b,
                                                   unsigned long long c) {
    unsigned long long d;
    asm("fma.rn.f32x2 %0, %1, %2, %3;" : "=l"(d) : "l"(a), "l"(b), "l"(c));
    return d;
}

// ---------- fast-but-accurate activations (EX2 + RCP, ~1e-6 err) ----------
__device__ __forceinline__ float rcpf_(float x) {
    float r; asm("rcp.approx.f32 %0, %1;" : "=f"(r) : "f"(x)); return r;
}
__device__ __forceinline__ float ex2f_(float x) {
    float r; asm("ex2.approx.f32 %0, %1;" : "=f"(r) : "f"(x)); return r;
}
__device__ __forceinline__ float sigm_(float x) {
    // 1 / (1 + 2^(-x*log2e))
    return rcpf_(1.0f + ex2f_(-1.4426950408889634f * x));
}
__device__ __forceinline__ float tanh_(float x) {
    // tanh = 1 - 2/(e^{2x}+1),  e^{2x} = 2^(x*2*log2e). Saturates gracefully at +-1.
    float e = ex2f_(2.8853900817779268f * x);
    return 1.0f - 2.0f * rcpf_(e + 1.0f);
}

// CTA: 128 threads = 4 warps. Lane = batch element (32 per CTA).
// Warp w handles gate type w (PyTorch order: 0=i, 1=f, 2=g, 3=o), 16 gates as
// 8 f32x2 pairs. Weights/bias packed in smem as {even,odd} gate pairs so each
// FFMA2 computes two gates of one element at once.
__global__ void __launch_bounds__(128, 1) lstm_fused_kernel(
    const float* __restrict__ x,
    const float* __restrict__ Wih0, const float* __restrict__ Whh0,
    const float* __restrict__ bih0, const float* __restrict__ bhh0,
    const float* __restrict__ Wih1, const float* __restrict__ Whh1,
    const float* __restrict__ bih1, const float* __restrict__ bhh1,
    const float* __restrict__ Wproj, const float* __restrict__ bproj,
    const float* __restrict__ gamma, const float* __restrict__ beta,
    float* __restrict__ out)
{
    // [layer][gatetype][k(0..15 = x-weights, 16..31 = h-weights)][gate-pair]
    __shared__ __align__(16) unsigned long long wpk[2][4][32][8];   // 16 KB
    __shared__ __align__(16) unsigned long long bpk[2][4][8];       // 512 B
    __shared__ float gact0[4][16][32];                              // 8 KB (layer-0 gates)
    __shared__ float gact1[4][16][32];                              // 8 KB (layer-1 gates)
    __shared__ __align__(16) unsigned long long hdup[2][16][32];    // 8 KB {h,h} duplicated

    const int tid = threadIdx.x;
    const int w   = tid >> 5;    // gate type / epilogue unit group
    const int l   = tid & 31;    // batch lane
    const int elem = blockIdx.x * 32 + l;

    // ---- pack weights into smem (once) ----
    for (int idx = tid; idx < 2048; idx += 128) {
        int p  = idx & 7;
        int k  = (idx >> 3) & 31;
        int t  = (idx >> 8) & 3;
        int ly = (idx >> 10) & 1;
        const float* Wi = ly ? Wih1 : Wih0;
        const float* Wh = ly ? Whh1 : Whh0;
        int g0 = t * 16 + 2 * p;          // even gate of the pair (row in W)
        float a, b;
        if (k < 16) { a = Wi[g0 * 16 + k];        b = Wi[g0 * 16 + 16 + k]; }
        else        { a = Wh[g0 * 16 + (k - 16)]; b = Wh[g0 * 16 + k];      }
        wpk[ly][t][k][p] = pk2(a, b);
    }
    for (int idx = tid; idx < 64; idx += 128) {
        int p  = idx & 7;
        int t  = (idx >> 3) & 3;
        int ly = (idx >> 5) & 1;
        const float* bi = ly ? bih1 : bih0;
        const float* bh = ly ? bhh1 : bhh0;
        int g0 = t * 16 + 2 * p;
        bpk[ly][t][p] = pk2(bi[g0] + bh[g0], bi[g0 + 1] + bh[g0 + 1]);
    }
    for (int idx = tid; idx < 1024; idx += 128)
        ((unsigned long long*)hdup)[idx] = 0ULL;

    float c0[4] = {0.f, 0.f, 0.f, 0.f};
    float c1[4] = {0.f, 0.f, 0.f, 0.f};
    __syncthreads();

    // ---- prefetch x for t=0 ----
    const float* xp = x + (size_t)elem * T_STEPS * HID;
    float4 xa = *(const float4*)(xp + 0);
    float4 xb = *(const float4*)(xp + 4);
    float4 xc = *(const float4*)(xp + 8);
    float4 xd = *(const float4*)(xp + 12);

#pragma unroll 1
    for (int t = 0; t < T_STEPS; ++t) {
        float xr[16];
        xr[0]=xa.x; xr[1]=xa.y; xr[2]=xa.z; xr[3]=xa.w;
        xr[4]=xb.x; xr[5]=xb.y; xr[6]=xb.z; xr[7]=xb.w;
        xr[8]=xc.x; xr[9]=xc.y; xr[10]=xc.z; xr[11]=xc.w;
        xr[12]=xd.x; xr[13]=xd.y; xr[14]=xd.z; xr[15]=xd.w;
        if (t + 1 < T_STEPS) {  // prefetch next step's x (hides DRAM/L2 latency)
            const float* xq = xp + (size_t)(t + 1) * HID;
            xa = *(const float4*)(xq + 0);
            xb = *(const float4*)(xq + 4);
            xc = *(const float4*)(xq + 8);
            xd = *(const float4*)(xq + 12);
        }

        unsigned long long acc[8];

        // ================= layer 0: gates =================
#pragma unroll
        for (int p = 0; p < 8; ++p) acc[p] = bpk[0][w][p];
#pragma unroll
        for (int k = 0; k < 16; ++k) {
            unsigned long long v = pk2(xr[k], xr[k]);
#pragma unroll
            for (int p = 0; p < 8; ++p) acc[p] = fma2(wpk[0][w][k][p], v, acc[p]);
        }
#pragma unroll
        for (int k = 0; k < 16; ++k) {
            unsigned long long v = hdup[0][k][l];
#pragma unroll
            for (int p = 0; p < 8; ++p) acc[p] = fma2(wpk[0][w][16 + k][p], v, acc[p]);
        }
        // activate + publish (warp-uniform branch on gate type)
#pragma unroll
        for (int p = 0; p < 8; ++p) {
            float a, b; upk2(acc[p], a, b);
            if (w == 2) { a = tanh_(a); b = tanh_(b); }
            else        { a = sigm_(a); b = sigm_(b); }
            gact0[w][2 * p][l]     = a;
            gact0[w][2 * p + 1][l] = b;
        }
        __syncthreads();
        // c/h update: warp w owns hidden units [4w, 4w+4)
#pragma unroll
        for (int j = 0; j < 4; ++j) {
            int u = 4 * w + j;
            float iv = gact0[0][u][l], fv = gact0[1][u][l];
            float gv = gact0[2][u][l], ov = gact0[3][u][l];
            c0[j] = fmaf(fv, c0[j], iv * gv);
            float h = ov * tanh_(c0[j]);
            hdup[0][u][l] = pk2(h, h);
        }
        __syncthreads();

        // ================= layer 1: gates (input = layer-0 h) =================
#pragma unroll
        for (int p = 0; p < 8; ++p) acc[p] = bpk[1][w][p];
#pragma unroll
        for (int k = 0; k < 16; ++k) {
            unsigned long long v = hdup[0][k][l];
#pragma unroll
            for (int p = 0; p < 8; ++p) acc[p] = fma2(wpk[1][w][k][p], v, acc[p]);
        }
#pragma unroll
        for (int k = 0; k < 16; ++k) {
            unsigned long long v = hdup[1][k][l];
#pragma unroll
            for (int p = 0; p < 8; ++p) acc[p] = fma2(wpk[1][w][16 + k][p], v, acc[p]);
        }
#pragma unroll
        for (int p = 0; p < 8; ++p) {
            float a, b; upk2(acc[p], a, b);
            if (w == 2) { a = tanh_(a); b = tanh_(b); }
            else        { a = sigm_(a); b = sigm_(b); }
            gact1[w][2 * p][l]     = a;
            gact1[w][2 * p + 1][l] = b;
        }
        __syncthreads();
#pragma unroll
        for (int j = 0; j < 4; ++j) {
            int u = 4 * w + j;
            float iv = gact1[0][u][l], fv = gact1[1][u][l];
            float gv = gact1[2][u][l], ov = gact1[3][u][l];
            c1[j] = fmaf(fv, c1[j], iv * gv);
            float h = ov * tanh_(c1[j]);
            hdup[1][u][l] = pk2(h, h);
        }
        __syncthreads();
        // (no 4th sync needed: hdup[1] next read is after two syncs of next step;
        //  gact buffers are per-layer so no reuse hazard across the loop edge)
    }

    // ---- projection + LayerNorm + tanh (once; warp 0, lane = elem) ----
    if (w == 0) {
        float hv[16];
#pragma unroll
        for (int k = 0; k < 16; ++k) {
            float a, b; upk2(hdup[1][k][l], a, b);
            hv[k] = a; (void)b;
        }
        float z[16];
        float mu = 0.f;
#pragma unroll
        for (int j = 0; j < 16; ++j) {
            float s = bproj[j];
#pragma unroll
            for (int k = 0; k < 16; ++k) s = fmaf(Wproj[j * 16 + k], hv[k], s);
            z[j] = s;
            mu += s;
        }
        mu *= (1.0f / 16.0f);
        float var = 0.f;
#pragma unroll
        for (int j = 0; j < 16; ++j) { float d = z[j] - mu; var = fmaf(d, d, var); }
        var *= (1.0f / 16.0f);
        float rs = rsqrtf(var + 1e-5f);
#pragma unroll
        for (int j = 0; j < 16; ++j) {
            float zn = (z[j] - mu) * rs * gamma[j] + beta[j];
            out[(size_t)elem * HID + j] = tanh_(zn);
        }
    }
}

extern "C" void kernel_launch(void* const* d_in, const int* in_sizes, int n_in,
                              void* d_out, int out_size) {
    const float* x     = (const float*)d_in[0];
    const float* Wih0  = (const float*)d_in[1];
    const float* Whh0  = (const float*)d_in[2];
    const float* bih0  = (const float*)d_in[3];
    const float* bhh0  = (const float*)d_in[4];
    const float* Wih1  = (const float*)d_in[5];
    const float* Whh1  = (const float*)d_in[6];
    const float* bih1  = (const float*)d_in[7];
    const float* bhh1  = (const float*)d_in[8];
    const float* Wproj = (const float*)d_in[9];
    const float* bproj = (const float*)d_in[10];
    const float* gamma = (const float*)d_in[11];
    const float* beta  = (const float*)d_in[12];
    float* out = (float*)d_out;

    int B = in_sizes[0] / (T_STEPS * HID);   // 4096
    int grid = B / 32;                       // 128 CTAs, 32 elems each

    lstm_fused_kernel<<<grid, 128>>>(x, Wih0, Whh0, bih0, bhh0,
                                     Wih1, Whh1, bih1, bhh1,
                                     Wproj, bproj, gamma, beta, out);
}

// round 2
// speedup vs baseline: 1.3348x; 1.3348x over previous
#include <cuda_runtime.h>

#define T_STEPS 512
#define HID 16
typedef unsigned long long ull;

// ---------- packed f32x2 helpers ----------
__device__ __forceinline__ ull pk2(float a, float b) {
    ull r; asm("mov.b64 %0, {%1,%2};" : "=l"(r) : "f"(a), "f"(b)); return r;
}
__device__ __forceinline__ ull dup2(float a) {
    ull r; asm("mov.b64 %0, {%1,%1};" : "=l"(r) : "f"(a)); return r;
}
__device__ __forceinline__ void upk2(ull v, float& a, float& b) {
    asm("mov.b64 {%0,%1}, %2;" : "=f"(a), "=f"(b) : "l"(v));
}
__device__ __forceinline__ ull fma2(ull a, ull b, ull c) {
    ull d; asm("fma.rn.f32x2 %0, %1, %2, %3;" : "=l"(d) : "l"(a), "l"(b), "l"(c));
    return d;
}

// ---------- activations (EX2+RCP, ~1e-6 abs err) ----------
__device__ __forceinline__ float rcpf_(float x) {
    float r; asm("rcp.approx.f32 %0, %1;" : "=f"(r) : "f"(x)); return r;
}
__device__ __forceinline__ float ex2f_(float x) {
    float r; asm("ex2.approx.f32 %0, %1;" : "=f"(r) : "f"(x)); return r;
}
__device__ __forceinline__ float sigm_(float x) {
    return rcpf_(1.0f + ex2f_(-1.4426950408889634f * x));
}
__device__ __forceinline__ float tanh_(float x) {
    float e = ex2f_(2.8853900817779268f * x);
    return 1.0f - 2.0f * rcpf_(e + 1.0f);
}

// CTA: 256 threads = 8 warps, 32 batch elems (lane = elem).
// Warp w owns hidden units {2w, 2w+1}: computes ALL 4 gate types for them.
// acc pairs: p=0:i(u0,u1) p=1:f(u0,u1) p=2:g(u0,u1) p=3:o(u0,u1).
// c/h update is fully warp-local -> only h is published to smem.
// Double-buffered h on step parity -> exactly ONE __syncthreads per step.
__global__ void __launch_bounds__(256, 1) lstm_fused2(
    const float* __restrict__ x,
    const float* __restrict__ Wih0, const float* __restrict__ Whh0,
    const float* __restrict__ bih0, const float* __restrict__ bhh0,
    const float* __restrict__ Wih1, const float* __restrict__ Whh1,
    const float* __restrict__ bih1, const float* __restrict__ bhh1,
    const float* __restrict__ Wproj, const float* __restrict__ bproj,
    const float* __restrict__ gamma, const float* __restrict__ beta,
    float* __restrict__ out)
{
    __shared__ __align__(16) ull wpk[2][8][32][4];   // [layer][warp][k][pair] 16 KB
    __shared__ __align__(16) ull bpk[2][8][4];       // 512 B
    __shared__ float h0s[2][16][32];                 // [parity][unit][lane] 4 KB
    __shared__ float h1s[2][16][32];                 // 4 KB

    const int tid = threadIdx.x;
    const int w   = tid >> 5;
    const int l   = tid & 31;
    const int elem = blockIdx.x * 32 + l;

    // ---- pack weights: pair = (gatetype p of unit 2w, unit 2w+1) ----
    for (int idx = tid; idx < 2048; idx += 256) {
        int p  = idx & 3;
        int k  = (idx >> 2) & 31;
        int ww = (idx >> 7) & 7;
        int ly = (idx >> 10) & 1;
        const float* Wi = ly ? Wih1 : Wih0;
        const float* Wh = ly ? Whh1 : Whh0;
        int r0 = p * 16 + 2 * ww, r1 = r0 + 1;
        float a, b;
        if (k < 16) { a = Wi[r0 * 16 + k];      b = Wi[r1 * 16 + k];      }
        else        { a = Wh[r0 * 16 + k - 16]; b = Wh[r1 * 16 + k - 16]; }
        wpk[ly][ww][k][p] = pk2(a, b);
    }
    for (int idx = tid; idx < 64; idx += 256) {
        int p  = idx & 3;
        int ww = (idx >> 2) & 7;
        int ly = (idx >> 5) & 1;
        const float* bi = ly ? bih1 : bih0;
        const float* bh = ly ? bhh1 : bhh0;
        int r0 = p * 16 + 2 * ww, r1 = r0 + 1;
        bpk[ly][ww][p] = pk2(bi[r0] + bh[r0], bi[r1] + bh[r1]);
    }
    for (int idx = tid; idx < 1024; idx += 256) {
        ((float*)h0s)[idx] = 0.f;
        ((float*)h1s)[idx] = 0.f;
    }

    float c00 = 0.f, c01 = 0.f;   // layer0 cell state, units 2w / 2w+1
    float c10 = 0.f, c11 = 0.f;   // layer1
    __syncthreads();

    const float* xp = x + (size_t)elem * T_STEPS * HID;
    float4 xa = *(const float4*)(xp + 0);
    float4 xb = *(const float4*)(xp + 4);
    float4 xc = *(const float4*)(xp + 8);
    float4 xd = *(const float4*)(xp + 12);
    float4 ya, yb, yc, yd;

#define HALF_STEP(PAR, XA, XB, XC, XD)                                          \
    {                                                                           \
        float xr[16];                                                           \
        xr[0]=XA.x; xr[1]=XA.y; xr[2]=XA.z;  xr[3]=XA.w;                        \
        xr[4]=XB.x; xr[5]=XB.y; xr[6]=XB.z;  xr[7]=XB.w;                        \
        xr[8]=XC.x; xr[9]=XC.y; xr[10]=XC.z; xr[11]=XC.w;                       \
        xr[12]=XD.x; xr[13]=XD.y; xr[14]=XD.z; xr[15]=XD.w;                     \
        ull a0 = bpk[0][w][0], a1 = bpk[0][w][1];                               \
        ull a2 = bpk[0][w][2], a3 = bpk[0][w][3];                               \
        _Pragma("unroll")                                                       \
        for (int k = 0; k < 16; ++k) {                                          \
            ull v = dup2(xr[k]);                                                \
            a0 = fma2(wpk[0][w][k][0], v, a0);                                  \
            a1 = fma2(wpk[0][w][k][1], v, a1);                                  \
            a2 = fma2(wpk[0][w][k][2], v, a2);                                  \
            a3 = fma2(wpk[0][w][k][3], v, a3);                                  \
        }                                                                       \
        _Pragma("unroll")                                                       \
        for (int k = 0; k < 16; ++k) {                                          \
            ull v = dup2(h0s[1 - (PAR)][k][l]);                                 \
            a0 = fma2(wpk[0][w][16 + k][0], v, a0);                             \
            a1 = fma2(wpk[0][w][16 + k][1], v, a1);                             \
            a2 = fma2(wpk[0][w][16 + k][2], v, a2);                             \
            a3 = fma2(wpk[0][w][16 + k][3], v, a3);                             \
        }                                                                       \
        {                                                                       \
            float ia, ib, fa, fb, ga, gb, oa, ob;                               \
            upk2(a0, ia, ib); upk2(a1, fa, fb);                                 \
            upk2(a2, ga, gb); upk2(a3, oa, ob);                                 \
            ia = sigm_(ia); ib = sigm_(ib);                                     \
            fa = sigm_(fa); fb = sigm_(fb);                                     \
            ga = tanh_(ga); gb = tanh_(gb);                                     \
            oa = sigm_(oa); ob = sigm_(ob);                                     \
            c00 = fmaf(fa, c00, ia * ga);                                       \
            c01 = fmaf(fb, c01, ib * gb);                                       \
            h0s[PAR][2 * w][l]     = oa * tanh_(c00);                           \
            h0s[PAR][2 * w + 1][l] = ob * tanh_(c01);                           \
        }                                                                       \
        __syncthreads();                                                        \
        a0 = bpk[1][w][0]; a1 = bpk[1][w][1];                                   \
        a2 = bpk[1][w][2]; a3 = bpk[1][w][3];                                   \
        _Pragma("unroll")                                                       \
        for (int k = 0; k < 16; ++k) {                                          \
            ull v = dup2(h0s[PAR][k][l]);                                       \
            a0 = fma2(wpk[1][w][k][0], v, a0);                                  \
            a1 = fma2(wpk[1][w][k][1], v, a1);                                  \
            a2 = fma2(wpk[1][w][k][2], v, a2);                                  \
            a3 = fma2(wpk[1][w][k][3], v, a3);                                  \
        }                                                                       \
        _Pragma("unroll")                                                       \
        for (int k = 0; k < 16; ++k) {                                          \
            ull v = dup2(h1s[1 - (PAR)][k][l]);                                 \
            a0 = fma2(wpk[1][w][16 + k][0], v, a0);                             \
            a1 = fma2(wpk[1][w][16 + k][1], v, a1);                             \
            a2 = fma2(wpk[1][w][16 + k][2], v, a2);                             \
            a3 = fma2(wpk[1][w][16 + k][3], v, a3);                             \
        }                                                                       \
        {                                                                       \
            float ia, ib, fa, fb, ga, gb, oa, ob;                               \
            upk2(a0, ia, ib); upk2(a1, fa, fb);                                 \
            upk2(a2, ga, gb); upk2(a3, oa, ob);                                 \
            ia = sigm_(ia); ib = sigm_(ib);                                     \
            fa = sigm_(fa); fb = sigm_(fb);                                     \
            ga = tanh_(ga); gb = tanh_(gb);                                     \
            oa = sigm_(oa); ob = sigm_(ob);                                     \
            c10 = fmaf(fa, c10, ia * ga);                                       \
            c11 = fmaf(fb, c11, ib * gb);                                       \
            h1s[PAR][2 * w][l]     = oa * tanh_(c10);                           \
            h1s[PAR][2 * w + 1][l] = ob * tanh_(c11);                           \
        }                                                                       \
    }

#pragma unroll 1
    for (int t = 0; t < T_STEPS; t += 2) {
        // prefetch x[t+1] before consuming x[t]
        {
            const float* xq = xp + (size_t)(t + 1) * HID;
            ya = *(const float4*)(xq + 0);
            yb = *(const float4*)(xq + 4);
            yc = *(const float4*)(xq + 8);
            yd = *(const float4*)(xq + 12);
        }
        HALF_STEP(0, xa, xb, xc, xd)
        if (t + 2 < T_STEPS) {
            const float* xq = xp + (size_t)(t + 2) * HID;
            xa = *(const float4*)(xq + 0);
            xb = *(const float4*)(xq + 4);
            xc = *(const float4*)(xq + 8);
            xd = *(const float4*)(xq + 12);
        }
        HALF_STEP(1, ya, yb, yc, yd)
    }
#undef HALF_STEP

    __syncthreads();  // make all warps' final h1 visible

    // ---- projection + LayerNorm + tanh (warp 0; lane = elem) ----
    if (w == 0) {
        float hv[16];
#pragma unroll
        for (int k = 0; k < 16; ++k) hv[k] = h1s[1][k][l];   // final parity = 1
        float z[16];
        float mu = 0.f;
#pragma unroll
        for (int j = 0; j < 16; ++j) {
            float s = bproj[j];
#pragma unroll
            for (int k = 0; k < 16; ++k) s = fmaf(Wproj[j * 16 + k], hv[k], s);
            z[j] = s;
            mu += s;
        }
        mu *= (1.0f / 16.0f);
        float var = 0.f;
#pragma unroll
        for (int j = 0; j < 16; ++j) { float d = z[j] - mu; var = fmaf(d, d, var); }
        var *= (1.0f / 16.0f);
        float rs = rsqrtf(var + 1e-5f);
#pragma unroll
        for (int j = 0; j < 16; ++j) {
            float zn = (z[j] - mu) * rs * gamma[j] + beta[j];
            out[(size_t)elem * HID + j] = tanh_(zn);
        }
    }
}

extern "C" void kernel_launch(void* const* d_in, const int* in_sizes, int n_in,
                              void* d_out, int out_size) {
    const float* x     = (const float*)d_in[0];
    const float* Wih0  = (const float*)d_in[1];
    const float* Whh0  = (const float*)d_in[2];
    const float* bih0  = (const float*)d_in[3];
    const float* bhh0  = (const float*)d_in[4];
    const float* Wih1  = (const float*)d_in[5];
    const float* Whh1  = (const float*)d_in[6];
    const float* bih1  = (const float*)d_in[7];
    const float* bhh1  = (const float*)d_in[8];
    const float* Wproj = (const float*)d_in[9];
    const float* bproj = (const float*)d_in[10];
    const float* gamma = (const float*)d_in[11];
    const float* beta  = (const float*)d_in[12];
    float* out = (float*)d_out;

    int B = in_sizes[0] / (T_STEPS * HID);   // 4096
    int grid = B / 32;                       // 128 CTAs

    lstm_fused2<<<grid, 256>>>(x, Wih0, Whh0, bih0, bhh0,
                               Wih1, Whh1, bih1, bhh1,
                               Wproj, bproj, gamma, beta, out);
}

// round 4
// speedup vs baseline: 1.4472x; 1.0841x over previous
#include <cuda_runtime.h>

#define TT 512
typedef unsigned long long ull;

// ---------- packed f32x2 helpers ----------
__device__ __forceinline__ ull pk2(float a, float b) {
    ull r; asm("mov.b64 %0, {%1,%2};" : "=l"(r) : "f"(a), "f"(b)); return r;
}
__device__ __forceinline__ float sum2(ull v) {
    float a, b; asm("mov.b64 {%0,%1}, %2;" : "=f"(a), "=f"(b) : "l"(v));
    return a + b;
}
__device__ __forceinline__ ull fma2(ull a, ull b, ull c) {
    ull d; asm("fma.rn.f32x2 %0, %1, %2, %3;" : "=l"(d) : "l"(a), "l"(b), "l"(c));
    return d;
}

// ---------- activations (EX2+RCP, ~1e-6 abs err; validated rel_err 2e-7) ----------
__device__ __forceinline__ float rcpf_(float x) {
    float r; asm("rcp.approx.f32 %0, %1;" : "=f"(r) : "f"(x)); return r;
}
__device__ __forceinline__ float ex2f_(float x) {
    float r; asm("ex2.approx.f32 %0, %1;" : "=f"(r) : "f"(x)); return r;
}
__device__ __forceinline__ float sigm_(float x) {
    return rcpf_(1.0f + ex2f_(-1.4426950408889634f * x));
}
__device__ __forceinline__ float tanh_(float x) {
    float e = ex2f_(2.8853900817779268f * x);
    return 1.0f - 2.0f * rcpf_(e + 1.0f);
}

// load 16 floats (64B, 16B-aligned) as 8 packed f32x2 ulls (works for gmem & smem)
__device__ __forceinline__ void ld8u(ull* v, const float* p) {
    const ulonglong2* q = (const ulonglong2*)p;
    ulonglong2 a = q[0], b = q[1], c = q[2], d = q[3];
    v[0]=a.x; v[1]=a.y; v[2]=b.x; v[3]=b.y; v[4]=c.x; v[5]=c.y; v[6]=d.x; v[7]=d.y;
}

// One LSTM-layer gate evaluation for 2 hidden units (this warp's), one lane-elem.
// wm[ww][kk][p]: p = unit*4 + gate(i,f,g,o); weights packed {W[row][2kk], W[row][2kk+1]}.
// kk 0..7 multiply vin (input pairs), kk 8..15 multiply hrec (recurrent pairs).
__device__ __forceinline__ void layer_eval(
    const ull (*__restrict__ wm)[16][8], int ww, const ull* __restrict__ bias,
    const ull* __restrict__ vin, const float* __restrict__ hrec_row,
    float& c0, float& c1, float* __restrict__ dst)
{
    ull a[8];
#pragma unroll
    for (int p = 0; p < 8; ++p) a[p] = bias[p];
#pragma unroll
    for (int kk = 0; kk < 8; ++kk) {
        ull v = vin[kk];
#pragma unroll
        for (int p = 0; p < 8; ++p) a[p] = fma2(wm[ww][kk][p], v, a[p]);
    }
    ull vh[8];
    ld8u(vh, hrec_row);
#pragma unroll
    for (int kk = 0; kk < 8; ++kk) {
        ull v = vh[kk];
#pragma unroll
        for (int p = 0; p < 8; ++p) a[p] = fma2(wm[ww][8 + kk][p], v, a[p]);
    }
    float i0 = sigm_(sum2(a[0])), f0 = sigm_(sum2(a[1]));
    float g0 = tanh_(sum2(a[2])), o0 = sigm_(sum2(a[3]));
    float i1 = sigm_(sum2(a[4])), f1 = sigm_(sum2(a[5]));
    float g1 = tanh_(sum2(a[6])), o1 = sigm_(sum2(a[7]));
    c0 = fmaf(f0, c0, i0 * g0);
    c1 = fmaf(f1, c1, i1 * g1);
    *(float2*)dst = make_float2(o0 * tanh_(c0), o1 * tanh_(c1));
}

// CTA: 512 threads = 16 warps, 32 elems (lane = elem), grid = 128.
// Warps 0-7: layer 0, units {2w, 2w+1}. Warps 8-15: layer 1, one step behind
// (software pipeline). One __syncthreads per step. h rows padded to 20 floats
// (80B stride) -> conflict-free LDS.128 vector reads.
__global__ void __launch_bounds__(512, 1) lstm_fused3(
    const float* __restrict__ x,
    const float* __restrict__ Wih0, const float* __restrict__ Whh0,
    const float* __restrict__ bih0, const float* __restrict__ bhh0,
    const float* __restrict__ Wih1, const float* __restrict__ Whh1,
    const float* __restrict__ bih1, const float* __restrict__ bhh1,
    const float* __restrict__ Wproj, const float* __restrict__ bproj,
    const float* __restrict__ gamma, const float* __restrict__ beta,
    float* __restrict__ out)
{
    __shared__ __align__(16) ull wA[8][16][8];          // layer0 weights, 8 KB
    __shared__ __align__(16) ull wB[8][16][8];          // layer1 weights, 8 KB
    __shared__ __align__(16) float h0b[2][32][20];      // [parity][lane][unit+pad]
    __shared__ __align__(16) float h1b[2][32][20];

    const int tid = threadIdx.x;
    const int w   = tid >> 5;
    const int l   = tid & 31;
    const int elem = blockIdx.x * 32 + l;

    // ---- pack weights: {W[row][2kk], W[row][2kk+1]}, p = unit*4 + gate ----
    for (int idx = tid; idx < 2048; idx += 512) {
        int p   = idx & 7;
        int kk  = (idx >> 3) & 15;
        int ww  = (idx >> 7) & 7;
        int grp = (idx >> 10) & 1;
        int u = 2 * ww + (p >> 2), g = p & 3, row = g * 16 + u;
        const float* Wi = grp ? Wih1 : Wih0;
        const float* Wh = grp ? Whh1 : Whh0;
        ull v;
        if (kk < 8) v = pk2(Wi[row * 16 + 2 * kk], Wi[row * 16 + 2 * kk + 1]);
        else        v = pk2(Wh[row * 16 + 2 * (kk - 8)], Wh[row * 16 + 2 * (kk - 8) + 1]);
        if (grp) wB[ww][kk][p] = v; else wA[ww][kk][p] = v;
    }
    // zero h buffers: each is 2*32*20 = 1280 floats (FIX: was 2560 -> OOB)
    for (int idx = tid; idx < 1280; idx += 512) {
        ((float*)h0b)[idx] = 0.f;
        ((float*)h1b)[idx] = 0.f;
    }

    // ---- bias in registers (warp-role specific) ----
    ull bias[8];
    {
        int wwb = w & 7;
        const float* bi = (w < 8) ? bih0 : bih1;
        const float* bh = (w < 8) ? bhh0 : bhh1;
#pragma unroll
        for (int p = 0; p < 8; ++p) {
            int u = 2 * wwb + (p >> 2), g = p & 3, row = g * 16 + u;
            bias[p] = pk2(bi[row] + bh[row], 0.f);
        }
    }
    float c0 = 0.f, c1 = 0.f;   // cell state for this warp's 2 units (its layer)
    __syncthreads();

    const float* xp = x + (size_t)elem * TT * 16;
    ull vx0[8], vx1[8];
    if (w < 8) ld8u(vx0, xp);   // x[0]

    const int ww = w & 7;

#pragma unroll 1
    for (int t0 = 0; t0 < TT; t0 += 2) {
        __syncthreads();
        // ---- global step t = t0 (parity 0) ----
        if (w < 8) {
            if (t0 + 1 < TT) ld8u(vx1, xp + (size_t)(t0 + 1) * 16);
            // A: h0[t0] = f(x[t0], h0[t0-1]@h0b[1]) -> h0b[0]
            layer_eval(wA, ww, bias, vx0, &h0b[1][l][0], c0, c1, &h0b[0][l][2 * ww]);
        } else if (t0 > 0) {
            // B: h1[t0-1] = f(h0[t0-1]@h0b[1], h1[t0-2]@h1b[0]) -> h1b[1]
            ull vin[8]; ld8u(vin, &h0b[1][l][0]);
            layer_eval(wB, ww, bias, vin, &h1b[0][l][0], c0, c1, &h1b[1][l][2 * ww]);
        }
        __syncthreads();
        // ---- global step t = t0+1 (parity 1) ----
        if (w < 8) {
            if (t0 + 2 < TT) ld8u(vx0, xp + (size_t)(t0 + 2) * 16);
            layer_eval(wA, ww, bias, vx1, &h0b[0][l][0], c0, c1, &h0b[1][l][2 * ww]);
        } else {
            ull vin[8]; ld8u(vin, &h0b[0][l][0]);
            layer_eval(wB, ww, bias, vin, &h1b[1][l][0], c0, c1, &h1b[0][l][2 * ww]);
        }
    }

    // ---- tail: B computes h1[TT-1] ----
    __syncthreads();
    if (w >= 8) {
        ull vin[8]; ld8u(vin, &h0b[1][l][0]);   // h0[TT-1]
        layer_eval(wB, ww, bias, vin, &h1b[0][l][0], c0, c1, &h1b[1][l][2 * ww]);
    }
    __syncthreads();

    // ---- projection + LayerNorm + tanh (warp 0; lane = elem) ----
    if (w == 0) {
        float hv[16];
#pragma unroll
        for (int k = 0; k < 16; ++k) hv[k] = h1b[1][l][k];
        float z[16];
        float mu = 0.f;
#pragma unroll
        for (int j = 0; j < 16; ++j) {
            float s = bproj[j];
#pragma unroll
            for (int k = 0; k < 16; ++k) s = fmaf(Wproj[j * 16 + k], hv[k], s);
            z[j] = s;
            mu += s;
        }
        mu *= (1.0f / 16.0f);
        float var = 0.f;
#pragma unroll
        for (int j = 0; j < 16; ++j) { float d = z[j] - mu; var = fmaf(d, d, var); }
        var *= (1.0f / 16.0f);
        float rs = rsqrtf(var + 1e-5f);
#pragma unroll
        for (int j = 0; j < 16; ++j) {
            float zn = (z[j] - mu) * rs * gamma[j] + beta[j];
            out[(size_t)elem * 16 + j] = tanh_(zn);
        }
    }
}

extern "C" void kernel_launch(void* const* d_in, const int* in_sizes, int n_in,
                              void* d_out, int out_size) {
    const float* x     = (const float*)d_in[0];
    const float* Wih0  = (const float*)d_in[1];
    const float* Whh0  = (const float*)d_in[2];
    const float* bih0  = (const float*)d_in[3];
    const float* bhh0  = (const float*)d_in[4];
    const float* Wih1  = (const float*)d_in[5];
    const float* Whh1  = (const float*)d_in[6];
    const float* bih1  = (const float*)d_in[7];
    const float* bhh1  = (const float*)d_in[8];
    const float* Wproj = (const float*)d_in[9];
    const float* bproj = (const float*)d_in[10];
    const float* gamma = (const float*)d_in[11];
    const float* beta  = (const float*)d_in[12];
    float* out = (float*)d_out;

    int B = in_sizes[0] / (TT * 16);   // 4096
    int grid = B / 32;                 // 128 CTAs

    lstm_fused3<<<grid, 512>>>(x, Wih0, Whh0, bih0, bhh0,
                               Wih1, Whh1, bih1, bhh1,
                               Wproj, bproj, gamma, beta, out);
}

// round 5
// speedup vs baseline: 1.5472x; 1.0691x over previous
#include <cuda_runtime.h>

#define TT 512
typedef unsigned long long ull;

// ---------- packed f32x2 helpers ----------
__device__ __forceinline__ ull pk2(float a, float b) {
    ull r; asm("mov.b64 %0, {%1,%2};" : "=l"(r) : "f"(a), "f"(b)); return r;
}
__device__ __forceinline__ float sum2(ull v) {
    float a, b; asm("mov.b64 {%0,%1}, %2;" : "=f"(a), "=f"(b) : "l"(v));
    return a + b;
}
__device__ __forceinline__ ull fma2(ull a, ull b, ull c) {
    ull d; asm("fma.rn.f32x2 %0, %1, %2, %3;" : "=l"(d) : "l"(a), "l"(b), "l"(c));
    return d;
}

// ---------- activations (EX2+RCP, validated rel_err ~2e-7 over full recurrence) ----------
__device__ __forceinline__ float rcpf_(float x) {
    float r; asm("rcp.approx.f32 %0, %1;" : "=f"(r) : "f"(x)); return r;
}
__device__ __forceinline__ float ex2f_(float x) {
    float r; asm("ex2.approx.f32 %0, %1;" : "=f"(r) : "f"(x)); return r;
}
__device__ __forceinline__ float sigm_(float x) {
    return rcpf_(1.0f + ex2f_(-1.4426950408889634f * x));
}
__device__ __forceinline__ float tanh_(float x) {
    float e = ex2f_(2.8853900817779268f * x);
    return 1.0f - 2.0f * rcpf_(e + 1.0f);
}

// load 16 floats (64B, 16B-aligned smem row) as 8 packed f32x2
__device__ __forceinline__ void ld8u(ull* v, const float* p) {
    const ulonglong2* q = (const ulonglong2*)p;
    ulonglong2 a = q[0], b = q[1], c = q[2], d = q[3];
    v[0]=a.x; v[1]=a.y; v[2]=b.x; v[3]=b.y; v[4]=c.x; v[5]=c.y; v[6]=d.x; v[7]=d.y;
}

// One LSTM cell eval for ONE batch element, whole warp cooperating.
// Lane j holds gate rows {j, j+32} in registers wv[0..15] / wv[16..31]
// (kk<8 -> W_ih pairs, kk>=8 -> W_hh pairs). Rows: i=0..15, f=16..31,
// g=32..47, o=48..63. So lane u<16: rows (i_u, g_u); lane u+16: (f_u, o_u).
// shfl.xor 16 pairs them; all lanes compute c/h redundantly; lanes 0..15 store h.
__device__ __forceinline__ void cell_task(
    const ull* __restrict__ wv, float b0, float b1,
    const float* __restrict__ vinrow, const float* __restrict__ recrow,
    float& c, float* __restrict__ dst, int lane)
{
    ull v0[8], v1[8];
    ld8u(v0, vinrow);
    ld8u(v1, recrow);
    ull a0 = 0ULL, a1 = 0ULL;
#pragma unroll
    for (int kk = 0; kk < 8; ++kk) {
        a0 = fma2(wv[kk],      v0[kk], a0);
        a1 = fma2(wv[16 + kk], v0[kk], a1);
    }
#pragma unroll
    for (int kk = 0; kk < 8; ++kk) {
        a0 = fma2(wv[8 + kk],  v1[kk], a0);
        a1 = fma2(wv[24 + kk], v1[kk], a1);
    }
    float s0 = sum2(a0) + b0;     // i (lane<16) or f (lane>=16): both sigmoid
    float s1 = sum2(a1) + b1;     // g (tanh) or o (sigmoid)
    float act0 = sigm_(s0);
    float act1 = (lane < 16) ? tanh_(s1) : sigm_(s1);
    float p0 = __shfl_xor_sync(0xffffffffu, act0, 16);
    float p1 = __shfl_xor_sync(0xffffffffu, act1, 16);
    float iv = (lane < 16) ? act0 : p0;
    float gv = (lane < 16) ? act1 : p1;
    float fv = (lane < 16) ? p0 : act0;
    float ov = (lane < 16) ? p1 : act1;
    c = fmaf(fv, c, iv * gv);
    float h = ov * tanh_(c);
    if (lane < 16) dst[lane] = h;
}

// CTA: 512 threads = 16 warps; 32 elems; grid 128.
// Warps 0-7: layer 0 ("A"), elems 4w..4w+3. Warps 8-15: layer 1 ("B"),
// one step behind (software pipeline, identical schedule to R4).
// Weights live in registers (zero weight-LDS traffic). x staged via smem
// double buffer, prefetched one step ahead (1 LDG + 1 STS per thread/step).
__global__ void __launch_bounds__(512, 1) lstm_reg(
    const float* __restrict__ x,
    const float* __restrict__ Wih0, const float* __restrict__ Whh0,
    const float* __restrict__ bih0, const float* __restrict__ bhh0,
    const float* __restrict__ Wih1, const float* __restrict__ Whh1,
    const float* __restrict__ bih1, const float* __restrict__ bhh1,
    const float* __restrict__ Wproj, const float* __restrict__ bproj,
    const float* __restrict__ gamma, const float* __restrict__ beta,
    float* __restrict__ out)
{
    __shared__ __align__(16) float h0b[2][32][16];   // [parity][elem][unit] 4 KB
    __shared__ __align__(16) float h1b[2][32][16];   // 4 KB
    __shared__ __align__(16) float xs[2][32][16];    // staged x, 4 KB

    const int tid = threadIdx.x;
    const int w    = tid >> 5;
    const int lane = tid & 31;
    const bool isA = (w < 8);
    const int ebase = (w & 7) * 4;            // this warp's 4 elems (CTA-local)
    const int elem0 = blockIdx.x * 32;

    // ---- weights into registers: lane -> gate rows {lane, lane+32} ----
    ull wv[32];
    float b0, b1;
    {
        const float* Wi = isA ? Wih0 : Wih1;
        const float* Wh = isA ? Whh0 : Whh1;
        const float* bi = isA ? bih0 : bih1;
        const float* bh = isA ? bhh0 : bhh1;
        int rA = lane, rB = lane + 32;
#pragma unroll
        for (int kk = 0; kk < 8; ++kk) {
            wv[kk]      = pk2(Wi[rA * 16 + 2 * kk], Wi[rA * 16 + 2 * kk + 1]);
            wv[8 + kk]  = pk2(Wh[rA * 16 + 2 * kk], Wh[rA * 16 + 2 * kk + 1]);
            wv[16 + kk] = pk2(Wi[rB * 16 + 2 * kk], Wi[rB * 16 + 2 * kk + 1]);
            wv[24 + kk] = pk2(Wh[rB * 16 + 2 * kk], Wh[rB * 16 + 2 * kk + 1]);
        }
        b0 = bi[rA] + bh[rA];
        b1 = bi[rB] + bh[rB];
    }

    // zero h buffers (2*32*16 = 1024 floats each)
    for (int idx = tid; idx < 1024; idx += 512) {
        ((float*)h0b)[idx] = 0.f;
        ((float*)h1b)[idx] = 0.f;
    }

    // ---- x staging: thread tid owns (elem se, feature sk) ----
    const int se = tid >> 4, sk = tid & 15;
    const float* xsrc = x + ((size_t)(elem0 + se) * TT) * 16 + sk;
    xs[0][se][sk] = xsrc[0];                 // x[0]
    float regb = xsrc[16];                   // x[1]
    float rega;

    float c[4] = {0.f, 0.f, 0.f, 0.f};
    __syncthreads();

#pragma unroll 1
    for (int t0 = 0; t0 < TT; t0 += 2) {
        // ===== S1: global step t0 (A reads xs[0] = x[t0]) =====
        xs[1][se][sk] = regb;                               // publish x[t0+1]
        {
            int tf = t0 + 2 < TT ? t0 + 2 : TT - 1;
            rega = xsrc[(size_t)tf * 16];                   // prefetch x[t0+2]
        }
        if (isA) {
#pragma unroll 1
            for (int e = 0; e < 4; ++e) {
                int E = ebase + e;
                cell_task(wv, b0, b1, &xs[0][E][0], &h0b[1][E][0],
                          c[e], &h0b[0][E][0], lane);
            }
        } else if (t0 > 0) {
#pragma unroll 1
            for (int e = 0; e < 4; ++e) {
                int E = ebase + e;
                cell_task(wv, b0, b1, &h0b[1][E][0], &h1b[0][E][0],
                          c[e], &h1b[1][E][0], lane);
            }
        }
        __syncthreads();
        // ===== S2: global step t0+1 (A reads xs[1] = x[t0+1]) =====
        xs[0][se][sk] = rega;                               // publish x[t0+2]
        {
            int tf = t0 + 3 < TT ? t0 + 3 : TT - 1;
            regb = xsrc[(size_t)tf * 16];                   // prefetch x[t0+3]
        }
        if (isA) {
#pragma unroll 1
            for (int e = 0; e < 4; ++e) {
                int E = ebase + e;
                cell_task(wv, b0, b1, &xs[1][E][0], &h0b[0][E][0],
                          c[e], &h0b[1][E][0], lane);
            }
        } else {
#pragma unroll 1
            for (int e = 0; e < 4; ++e) {
                int E = ebase + e;
                cell_task(wv, b0, b1, &h0b[0][E][0], &h1b[1][E][0],
                          c[e], &h1b[0][E][0], lane);
            }
        }
        __syncthreads();
    }

    // ---- tail: B computes h1[TT-1] from h0[TT-1]@h0b[1], h1[TT-2]@h1b[0] ----
    if (!isA) {
#pragma unroll 1
        for (int e = 0; e < 4; ++e) {
            int E = ebase + e;
            cell_task(wv, b0, b1, &h0b[1][E][0], &h1b[0][E][0],
                      c[e], &h1b[1][E][0], lane);
        }
    }
    __syncthreads();

    // ---- projection + LayerNorm + tanh (warp 0; lane = elem) ----
    if (w == 0) {
        float hv[16];
#pragma unroll
        for (int k = 0; k < 16; ++k) hv[k] = h1b[1][lane][k];
        float z[16];
        float mu = 0.f;
#pragma unroll
        for (int j = 0; j < 16; ++j) {
            float s = bproj[j];
#pragma unroll
            for (int k = 0; k < 16; ++k) s = fmaf(Wproj[j * 16 + k], hv[k], s);
            z[j] = s;
            mu += s;
        }
        mu *= (1.0f / 16.0f);
        float var = 0.f;
#pragma unroll
        for (int j = 0; j < 16; ++j) { float d = z[j] - mu; var = fmaf(d, d, var); }
        var *= (1.0f / 16.0f);
        float rs = rsqrtf(var + 1e-5f);
#pragma unroll
        for (int j = 0; j < 16; ++j) {
            float zn = (z[j] - mu) * rs * gamma[j] + beta[j];
            out[(size_t)(elem0 + lane) * 16 + j] = tanh_(zn);
        }
    }
}

extern "C" void kernel_launch(void* const* d_in, const int* in_sizes, int n_in,
                              void* d_out, int out_size) {
    const float* x     = (const float*)d_in[0];
    const float* Wih0  = (const float*)d_in[1];
    const float* Whh0  = (const float*)d_in[2];
    const float* bih0  = (const float*)d_in[3];
    const float* bhh0  = (const float*)d_in[4];
    const float* Wih1  = (const float*)d_in[5];
    const float* Whh1  = (const float*)d_in[6];
    const float* bih1  = (const float*)d_in[7];
    const float* bhh1  = (const float*)d_in[8];
    const float* Wproj = (const float*)d_in[9];
    const float* bproj = (const float*)d_in[10];
    const float* gamma = (const float*)d_in[11];
    const float* beta  = (const float*)d_in[12];
    float* out = (float*)d_out;

    int B = in_sizes[0] / (TT * 16);   // 4096
    int grid = B / 32;                 // 128 CTAs

    lstm_reg<<<grid, 512>>>(x, Wih0, Whh0, bih0, bhh0,
                            Wih1, Whh1, bih1, bhh1,
                            Wproj, bproj, gamma, beta, out);
}

// round 6
// speedup vs baseline: 2.1513x; 1.3904x over previous
#include <cuda_runtime.h>

#define TT 512
typedef unsigned long long ull;

// ---------- packed f32x2 helpers ----------
__device__ __forceinline__ ull pk2(float a, float b) {
    ull r; asm("mov.b64 %0, {%1,%2};" : "=l"(r) : "f"(a), "f"(b)); return r;
}
__device__ __forceinline__ float sum2(ull v) {
    float a, b; asm("mov.b64 {%0,%1}, %2;" : "=f"(a), "=f"(b) : "l"(v));
    return a + b;
}
__device__ __forceinline__ ull fma2(ull a, ull b, ull c) {
    ull d; asm("fma.rn.f32x2 %0, %1, %2, %3;" : "=l"(d) : "l"(a), "l"(b), "l"(c));
    return d;
}
__device__ __forceinline__ ull add2(ull a, ull b) {
    ull d; asm("add.rn.f32x2 %0, %1, %2;" : "=l"(d) : "l"(a), "l"(b));
    return d;
}

// ---------- activations (EX2+RCP; validated rel_err ~2e-7 over full recurrence) ----------
__device__ __forceinline__ float rcpf_(float x) {
    float r; asm("rcp.approx.f32 %0, %1;" : "=f"(r) : "f"(x)); return r;
}
__device__ __forceinline__ float ex2f_(float x) {
    float r; asm("ex2.approx.f32 %0, %1;" : "=f"(r) : "f"(x)); return r;
}
__device__ __forceinline__ float tanh_(float x) {
    float e = ex2f_(2.8853900817779268f * x);
    return 1.0f - 2.0f * rcpf_(e + 1.0f);
}
#define L2E 1.4426950408889634f

// load 16 floats (64B, 16B-aligned smem row) as 8 packed f32x2
__device__ __forceinline__ void ld8u(ull* v, const float* p) {
    const ulonglong2* q = (const ulonglong2*)p;
    ulonglong2 a = q[0], b = q[1], c = q[2], d = q[3];
    v[0]=a.x; v[1]=a.y; v[2]=b.x; v[3]=b.y; v[4]=c.x; v[5]=c.y; v[6]=d.x; v[7]=d.y;
}

// One LSTM cell eval for ONE batch element, whole warp cooperating.
// Lane j holds gate rows {j, j+32} in registers (rows: i=0..15 f=16..31
// g=32..47 o=48..63 -> lane u<16: (i_u, g_u); lane u+16: (f_u, o_u)).
// k1/actm/actb are hoisted per-lane constants implementing
// act1 = tanh(s1) for lanes<16, sigmoid(s1) otherwise, via tanh(x)=2*sigm(2x)-1.
__device__ __forceinline__ void task1(
    const ull* __restrict__ wv, ull bi0, ull bi1,
    const float* __restrict__ inrow, const float* __restrict__ recrow,
    float& c, float* __restrict__ dst,
    float k1, float actm, float actb, bool lo, int lane)
{
    ull v0[8], v1[8];
    ld8u(v0, inrow);
    ld8u(v1, recrow);
    ull a0 = bi0, a1 = bi1, a0b = 0ULL, a1b = 0ULL;   // 4 independent 8-deep chains
#pragma unroll
    for (int kk = 0; kk < 8; ++kk) {
        a0  = fma2(wv[kk],      v0[kk], a0);
        a1  = fma2(wv[16 + kk], v0[kk], a1);
        a0b = fma2(wv[8 + kk],  v1[kk], a0b);
        a1b = fma2(wv[24 + kk], v1[kk], a1b);
    }
    float s0 = sum2(add2(a0, a0b));
    float s1 = sum2(add2(a1, a1b));
    float act0 = rcpf_(1.0f + ex2f_(-L2E * s0));                 // sigmoid
    float act1 = fmaf(actm, rcpf_(1.0f + ex2f_(k1 * s1)), actb); // tanh or sigm
    float p0 = __shfl_xor_sync(0xffffffffu, act0, 16);
    float p1 = __shfl_xor_sync(0xffffffffu, act1, 16);
    float fv = lo ? p0 : act0;
    float iv = lo ? act0 : p0;
    float gv = lo ? act1 : p1;
    float ov = lo ? p1 : act1;
    c = fmaf(fv, c, iv * gv);
    float h = ov * tanh_(c);
    if (lo) dst[lane] = h;
}

// 4 elems, fully unrolled -> 4 independent task chains for the scheduler.
__device__ __forceinline__ void cell4(
    const ull* __restrict__ wv, ull bi0, ull bi1,
    const float* __restrict__ inb, const float* __restrict__ recb,
    float* __restrict__ c, float* __restrict__ dstb,
    float k1, float actm, float actb, bool lo, int lane)
{
#pragma unroll
    for (int e = 0; e < 4; ++e)
        task1(wv, bi0, bi1, inb + 16 * e, recb + 16 * e,
              c[e], dstb + 16 * e, k1, actm, actb, lo, lane);
}

// CTA: 512 threads = 16 warps; 32 elems; grid 128.
// Warps 0-7: layer 0 ("A"), elems 4w..4w+3. Warps 8-15: layer 1 ("B"),
// one step behind (software pipeline). Weights in registers; x staged through
// a double-buffered smem tile, prefetched one step ahead.
__global__ void __launch_bounds__(512, 1) lstm_reg2(
    const float* __restrict__ x,
    const float* __restrict__ Wih0, const float* __restrict__ Whh0,
    const float* __restrict__ bih0, const float* __restrict__ bhh0,
    const float* __restrict__ Wih1, const float* __restrict__ Whh1,
    const float* __restrict__ bih1, const float* __restrict__ bhh1,
    const float* __restrict__ Wproj, const float* __restrict__ bproj,
    const float* __restrict__ gamma, const float* __restrict__ beta,
    float* __restrict__ out)
{
    __shared__ __align__(16) float h0b[2][32][16];   // [parity][elem][unit]
    __shared__ __align__(16) float h1b[2][32][16];
    __shared__ __align__(16) float xs[2][32][16];    // staged x

    const int tid = threadIdx.x;
    const int w    = tid >> 5;
    const int lane = tid & 31;
    const bool isA = (w < 8);
    const bool lo  = (lane < 16);
    const int ebase = (w & 7) * 4;
    const int elem0 = blockIdx.x * 32;

    // ---- weights into registers: lane -> gate rows {lane, lane+32} ----
    ull wv[32];
    ull bi0, bi1;
    {
        const float* Wi = isA ? Wih0 : Wih1;
        const float* Wh = isA ? Whh0 : Whh1;
        const float* bi = isA ? bih0 : bih1;
        const float* bh = isA ? bhh0 : bhh1;
        int rA = lane, rB = lane + 32;
#pragma unroll
        for (int kk = 0; kk < 8; ++kk) {
            wv[kk]      = pk2(Wi[rA * 16 + 2 * kk], Wi[rA * 16 + 2 * kk + 1]);
            wv[8 + kk]  = pk2(Wh[rA * 16 + 2 * kk], Wh[rA * 16 + 2 * kk + 1]);
            wv[16 + kk] = pk2(Wi[rB * 16 + 2 * kk], Wi[rB * 16 + 2 * kk + 1]);
            wv[24 + kk] = pk2(Wh[rB * 16 + 2 * kk], Wh[rB * 16 + 2 * kk + 1]);
        }
        bi0 = pk2(bi[rA] + bh[rA], 0.f);
        bi1 = pk2(bi[rB] + bh[rB], 0.f);
    }
    // hoisted activation-select constants (act1: tanh for lanes<16 else sigm)
    const float actm = lo ? 2.0f : 1.0f;
    const float actb = lo ? -1.0f : 0.0f;
    const float k1   = -L2E * actm;

    for (int idx = tid; idx < 1024; idx += 512) {
        ((float*)h0b)[idx] = 0.f;
        ((float*)h1b)[idx] = 0.f;
    }

    // ---- x staging: thread owns (elem se, feature sk) ----
    const int se = tid >> 4, sk = tid & 15;
    const float* xsrc = x + ((size_t)(elem0 + se) * TT) * 16 + sk;
    xs[0][se][sk] = xsrc[0];
    float regb = xsrc[16];
    float rega;

    float c[4] = {0.f, 0.f, 0.f, 0.f};

    // per-warp row base pointers (e-offsets fold into LDS immediates)
    const float* inS1  = isA ? &xs[0][ebase][0]  : &h0b[1][ebase][0];
    const float* recS1 = isA ? &h0b[1][ebase][0] : &h1b[0][ebase][0];
    float*       dstS1 = isA ? &h0b[0][ebase][0] : &h1b[1][ebase][0];
    const float* inS2  = isA ? &xs[1][ebase][0]  : &h0b[0][ebase][0];
    const float* recS2 = isA ? &h0b[0][ebase][0] : &h1b[1][ebase][0];
    float*       dstS2 = isA ? &h0b[1][ebase][0] : &h1b[0][ebase][0];

    __syncthreads();

#pragma unroll 1
    for (int t0 = 0; t0 < TT; t0 += 2) {
        // ===== S1: global step t0 =====
        xs[1][se][sk] = regb;                               // publish x[t0+1]
        {
            int tf = t0 + 2 < TT ? t0 + 2 : TT - 1;
            rega = xsrc[(size_t)tf * 16];                   // prefetch x[t0+2]
        }
        if (isA || t0 > 0)
            cell4(wv, bi0, bi1, inS1, recS1, c, dstS1, k1, actm, actb, lo, lane);
        __syncthreads();
        // ===== S2: global step t0+1 =====
        xs[0][se][sk] = rega;                               // publish x[t0+2]
        {
            int tf = t0 + 3 < TT ? t0 + 3 : TT - 1;
            regb = xsrc[(size_t)tf * 16];                   // prefetch x[t0+3]
        }
        cell4(wv, bi0, bi1, inS2, recS2, c, dstS2, k1, actm, actb, lo, lane);
        __syncthreads();
    }

    // ---- tail: B computes h1[TT-1] (same operands as S1) ----
    if (!isA)
        cell4(wv, bi0, bi1, inS1, recS1, c, dstS1, k1, actm, actb, lo, lane);
    __syncthreads();

    // ---- projection + LayerNorm + tanh (warp 0; lane = elem) ----
    if (w == 0) {
        float hv[16];
#pragma unroll
        for (int k = 0; k < 16; ++k) hv[k] = h1b[1][lane][k];
        float z[16];
        float mu = 0.f;
#pragma unroll
        for (int j = 0; j < 16; ++j) {
            float s = bproj[j];
#pragma unroll
            for (int k = 0; k < 16; ++k) s = fmaf(Wproj[j * 16 + k], hv[k], s);
            z[j] = s;
            mu += s;
        }
        mu *= (1.0f / 16.0f);
        float var = 0.f;
#pragma unroll
        for (int j = 0; j < 16; ++j) { float d = z[j] - mu; var = fmaf(d, d, var); }
        var *= (1.0f / 16.0f);
        float rs = rsqrtf(var + 1e-5f);
#pragma unroll
        for (int j = 0; j < 16; ++j) {
            float zn = (z[j] - mu) * rs * gamma[j] + beta[j];
            out[(size_t)(elem0 + lane) * 16 + j] = tanh_(zn);
        }
    }
}

extern "C" void kernel_launch(void* const* d_in, const int* in_sizes, int n_in,
                              void* d_out, int out_size) {
    const float* x     = (const float*)d_in[0];
    const float* Wih0  = (const float*)d_in[1];
    const float* Whh0  = (const float*)d_in[2];
    const float* bih0  = (const float*)d_in[3];
    const float* bhh0  = (const float*)d_in[4];
    const float* Wih1  = (const float*)d_in[5];
    const float* Whh1  = (const float*)d_in[6];
    const float* bih1  = (const float*)d_in[7];
    const float* bhh1  = (const float*)d_in[8];
    const float* Wproj = (const float*)d_in[9];
    const float* bproj = (const float*)d_in[10];
    const float* gamma = (const float*)d_in[11];
    const float* beta  = (const float*)d_in[12];
    float* out = (float*)d_out;

    int B = in_sizes[0] / (TT * 16);   // 4096
    int grid = B / 32;                 // 128 CTAs

    lstm_reg2<<<grid, 512>>>(x, Wih0, Whh0, bih0, bhh0,
                             Wih1, Whh1, bih1, bhh1,
                             Wproj, bproj, gamma, beta, out);
}

// round 7
// speedup vs baseline: 2.1985x; 1.0219x over previous
#include <cuda_runtime.h>

#define TT 512
typedef unsigned long long ull;

// ---------- packed f32x2 helpers ----------
__device__ __forceinline__ ull pk2(float a, float b) {
    ull r; asm("mov.b64 %0, {%1,%2};" : "=l"(r) : "f"(a), "f"(b)); return r;
}
__device__ __forceinline__ float sum2(ull v) {
    float a, b; asm("mov.b64 {%0,%1}, %2;" : "=f"(a), "=f"(b) : "l"(v));
    return a + b;
}
__device__ __forceinline__ ull fma2(ull a, ull b, ull c) {
    ull d; asm("fma.rn.f32x2 %0, %1, %2, %3;" : "=l"(d) : "l"(a), "l"(b), "l"(c));
    return d;
}
__device__ __forceinline__ ull add2(ull a, ull b) {
    ull d; asm("add.rn.f32x2 %0, %1, %2;" : "=l"(d) : "l"(a), "l"(b));
    return d;
}

// ---------- activations (EX2+RCP; validated rel_err ~2e-7 over full recurrence) ----------
__device__ __forceinline__ float rcpf_(float x) {
    float r; asm("rcp.approx.f32 %0, %1;" : "=f"(r) : "f"(x)); return r;
}
__device__ __forceinline__ float ex2f_(float x) {
    float r; asm("ex2.approx.f32 %0, %1;" : "=f"(r) : "f"(x)); return r;
}
__device__ __forceinline__ float tanh_(float x) {
    float e = ex2f_(2.8853900817779268f * x);
    return 1.0f - 2.0f * rcpf_(e + 1.0f);
}
#define L2E 1.4426950408889634f

// pairwise named barrier: warps w and w+8 share id (w&7)+1, 64 threads
#define PBAR(id) asm volatile("bar.sync %0, %1;" :: "r"(id), "r"(64) : "memory")

// load 16 floats (64B, 16B-aligned smem row) as 8 packed f32x2
__device__ __forceinline__ void ld8u(ull* v, const float* p) {
    const ulonglong2* q = (const ulonglong2*)p;
    ulonglong2 a = q[0], b = q[1], c = q[2], d = q[3];
    v[0]=a.x; v[1]=a.y; v[2]=b.x; v[3]=b.y; v[4]=c.x; v[5]=c.y; v[6]=d.x; v[7]=d.y;
}

// One LSTM cell eval for ONE batch element, whole warp cooperating.
// Lane j holds gate rows {j, j+32} in registers (rows: i=0..15 f=16..31
// g=32..47 o=48..63 -> lane u<16: (i_u, g_u); lane u+16: (f_u, o_u)).
__device__ __forceinline__ void task1(
    const ull* __restrict__ wv, ull bi0, ull bi1,
    const float* __restrict__ inrow, const float* __restrict__ recrow,
    float& c, float* __restrict__ dst,
    float k1, float actm, float actb, bool lo, int lane)
{
    ull v0[8], v1[8];
    ld8u(v0, inrow);
    ld8u(v1, recrow);
    ull a0 = bi0, a1 = bi1, a0b = 0ULL, a1b = 0ULL;   // 4 independent 8-deep chains
#pragma unroll
    for (int kk = 0; kk < 8; ++kk) {
        a0  = fma2(wv[kk],      v0[kk], a0);
        a1  = fma2(wv[16 + kk], v0[kk], a1);
        a0b = fma2(wv[8 + kk],  v1[kk], a0b);
        a1b = fma2(wv[24 + kk], v1[kk], a1b);
    }
    float s0 = sum2(add2(a0, a0b));
    float s1 = sum2(add2(a1, a1b));
    float act0 = rcpf_(1.0f + ex2f_(-L2E * s0));                 // sigmoid
    float act1 = fmaf(actm, rcpf_(1.0f + ex2f_(k1 * s1)), actb); // tanh or sigm
    float p0 = __shfl_xor_sync(0xffffffffu, act0, 16);
    float p1 = __shfl_xor_sync(0xffffffffu, act1, 16);
    float fv = lo ? p0 : act0;
    float iv = lo ? act0 : p0;
    float gv = lo ? act1 : p1;
    float ov = lo ? p1 : act1;
    c = fmaf(fv, c, iv * gv);
    float h = ov * tanh_(c);
    if (lo) dst[lane] = h;
}

__device__ __forceinline__ void cell4(
    const ull* __restrict__ wv, ull bi0, ull bi1,
    const float* __restrict__ inb, const float* __restrict__ recb,
    float* __restrict__ c, float* __restrict__ dstb,
    float k1, float actm, float actb, bool lo, int lane)
{
#pragma unroll
    for (int e = 0; e < 4; ++e)
        task1(wv, bi0, bi1, inb + 16 * e, recb + 16 * e,
              c[e], dstb + 16 * e, k1, actm, actb, lo, lane);
}

// CTA: 512 threads = 16 warps; 32 elems; grid 128.
// Warps 0-7: layer 0 ("A"), elems 4w..4w+3. Warps 8-15: layer 1 ("B"),
// one step behind. A-warp w <-> B-warp w+8 are an independent producer/
// consumer pair: sync via named barrier (w&7)+1 with 64 threads -> no
// 16-warp convoy. x staging is warp-private to each A warp.
__global__ void __launch_bounds__(512, 1) lstm_pair(
    const float* __restrict__ x,
    const float* __restrict__ Wih0, const float* __restrict__ Whh0,
    const float* __restrict__ bih0, const float* __restrict__ bhh0,
    const float* __restrict__ Wih1, const float* __restrict__ Whh1,
    const float* __restrict__ bih1, const float* __restrict__ bhh1,
    const float* __restrict__ Wproj, const float* __restrict__ bproj,
    const float* __restrict__ gamma, const float* __restrict__ beta,
    float* __restrict__ out)
{
    __shared__ __align__(16) float h0b[2][32][16];   // [parity][elem][unit]
    __shared__ __align__(16) float h1b[2][32][16];
    __shared__ __align__(16) float4 xs4[2][8][16];   // [parity][A-warp][e*4+q]

    const int tid = threadIdx.x;
    const int w    = tid >> 5;
    const int lane = tid & 31;
    const bool isA = (w < 8);
    const bool lo  = (lane < 16);
    const int wp   = w & 7;
    const int ebase = wp * 4;
    const int elem0 = blockIdx.x * 32;
    const int bid = wp + 1;                      // named barrier id, 1..8

    // ---- weights into registers: lane -> gate rows {lane, lane+32} ----
    ull wv[32];
    ull bi0, bi1;
    {
        const float* Wi = isA ? Wih0 : Wih1;
        const float* Wh = isA ? Whh0 : Whh1;
        const float* bi = isA ? bih0 : bih1;
        const float* bh = isA ? bhh0 : bhh1;
        int rA = lane, rB = lane + 32;
#pragma unroll
        for (int kk = 0; kk < 8; ++kk) {
            wv[kk]      = pk2(Wi[rA * 16 + 2 * kk], Wi[rA * 16 + 2 * kk + 1]);
            wv[8 + kk]  = pk2(Wh[rA * 16 + 2 * kk], Wh[rA * 16 + 2 * kk + 1]);
            wv[16 + kk] = pk2(Wi[rB * 16 + 2 * kk], Wi[rB * 16 + 2 * kk + 1]);
            wv[24 + kk] = pk2(Wh[rB * 16 + 2 * kk], Wh[rB * 16 + 2 * kk + 1]);
        }
        bi0 = pk2(bi[rA] + bh[rA], 0.f);
        bi1 = pk2(bi[rB] + bh[rB], 0.f);
    }
    const float actm = lo ? 2.0f : 1.0f;
    const float actb = lo ? -1.0f : 0.0f;
    const float k1   = -L2E * actm;

    for (int idx = tid; idx < 1024; idx += 512) {
        ((float*)h0b)[idx] = 0.f;
        ((float*)h1b)[idx] = 0.f;
    }

    // ---- warp-private x staging (A warps, lanes 0-15): lane -> (elem e=lane>>2,
    // quad q=lane&3). One LDG.128 + one STS.128 per step.
    const float4* xq = (const float4*)x;  // dummy init for B warps
    float4 xnA, xnB;
    if (isA) {
        int e = lane >> 2, q = lane & 3;
        xq = (const float4*)(x + ((size_t)(elem0 + ebase + e) * TT) * 16) + q;
        if (lo) {
            xs4[0][wp][lane] = xq[0];   // x[0]
            xnB = xq[4];                // x[1]
        }
    }

    float c[4] = {0.f, 0.f, 0.f, 0.f};

    // per-warp row base pointers
    const float* inS1  = isA ? (const float*)&xs4[0][wp][0] : &h0b[1][ebase][0];
    const float* recS1 = isA ? &h0b[1][ebase][0] : &h1b[0][ebase][0];
    float*       dstS1 = isA ? &h0b[0][ebase][0] : &h1b[1][ebase][0];
    const float* inS2  = isA ? (const float*)&xs4[1][wp][0] : &h0b[0][ebase][0];
    const float* recS2 = isA ? &h0b[0][ebase][0] : &h1b[1][ebase][0];
    float*       dstS2 = isA ? &h0b[1][ebase][0] : &h1b[0][ebase][0];

    __syncthreads();

#pragma unroll 1
    for (int t0 = 0; t0 < TT; t0 += 2) {
        // ===== S1: global step t0 =====
        if (isA) {
            if (lo) {
                xs4[1][wp][lane] = xnB;                    // publish x[t0+1]
                int tf = t0 + 2 < TT ? t0 + 2 : TT - 1;
                xnA = xq[(size_t)tf * 4];                  // prefetch x[t0+2]
            }
            cell4(wv, bi0, bi1, inS1, recS1, c, dstS1, k1, actm, actb, lo, lane);
        } else if (t0 > 0) {
            cell4(wv, bi0, bi1, inS1, recS1, c, dstS1, k1, actm, actb, lo, lane);
        }
        PBAR(bid);
        // ===== S2: global step t0+1 =====
        if (isA && lo) {
            xs4[0][wp][lane] = xnA;                        // publish x[t0+2]
            int tf = t0 + 3 < TT ? t0 + 3 : TT - 1;
            xnB = xq[(size_t)tf * 4];                      // prefetch x[t0+3]
        }
        cell4(wv, bi0, bi1, inS2, recS2, c, dstS2, k1, actm, actb, lo, lane);
        PBAR(bid);
    }

    // ---- tail: B computes h1[TT-1] (same operand roles as S1) ----
    if (!isA)
        cell4(wv, bi0, bi1, inS1, recS1, c, dstS1, k1, actm, actb, lo, lane);
    __syncthreads();

    // ---- projection + LayerNorm + tanh (warp 0; lane = elem) ----
    if (w == 0) {
        float hv[16];
#pragma unroll
        for (int k = 0; k < 16; ++k) hv[k] = h1b[1][lane][k];
        float z[16];
        float mu = 0.f;
#pragma unroll
        for (int j = 0; j < 16; ++j) {
            float s = bproj[j];
#pragma unroll
            for (int k = 0; k < 16; ++k) s = fmaf(Wproj[j * 16 + k], hv[k], s);
            z[j] = s;
            mu += s;
        }
        mu *= (1.0f / 16.0f);
        float var = 0.f;
#pragma unroll
        for (int j = 0; j < 16; ++j) { float d = z[j] - mu; var = fmaf(d, d, var); }
        var *= (1.0f / 16.0f);
        float rs = rsqrtf(var + 1e-5f);
#pragma unroll
        for (int j = 0; j < 16; ++j) {
            float zn = (z[j] - mu) * rs * gamma[j] + beta[j];
            out[(size_t)(elem0 + lane) * 16 + j] = tanh_(zn);
        }
    }
}

extern "C" void kernel_launch(void* const* d_in, const int* in_sizes, int n_in,
                              void* d_out, int out_size) {
    const float* x     = (const float*)d_in[0];
    const float* Wih0  = (const float*)d_in[1];
    const float* Whh0  = (const float*)d_in[2];
    const float* bih0  = (const float*)d_in[3];
    const float* bhh0  = (const float*)d_in[4];
    const float* Wih1  = (const float*)d_in[5];
    const float* Whh1  = (const float*)d_in[6];
    const float* bih1  = (const float*)d_in[7];
    const float* bhh1  = (const float*)d_in[8];
    const float* Wproj = (const float*)d_in[9];
    const float* bproj = (const float*)d_in[10];
    const float* gamma = (const float*)d_in[11];
    const float* beta  = (const float*)d_in[12];
    float* out = (float*)d_out;

    int B = in_sizes[0] / (TT * 16);   // 4096
    int grid = B / 32;                 // 128 CTAs

    lstm_pair<<<grid, 512>>>(x, Wih0, Whh0, bih0, bhh0,
                             Wih1, Whh1, bih1, bhh1,
                             Wproj, bproj, gamma, beta, out);
}